// round 9
// baseline (speedup 1.0000x reference)
#include <cuda_runtime.h>
#include <cuda_fp16.h>

#define N_NODES 100000
#define N_EDGES 100000
#define NNZV    1600000
#define D_IN    128
#define D_OUT   128
#define PAD     64        // slots per row; Poisson(16) => P(deg>64) ~ 1e-20/bucket

// ---- scratch (device globals; allocation is forbidden) ----
__device__ __align__(16) __half2 g_hh2[N_NODES * 64];   // x @ W, fp16   (25.6 MB)
__device__ __align__(16) __half2 g_efh2[N_EDGES * 64];  // e_feat, fp16  (25.6 MB)
__device__ int g_cntN[N_NODES];            // cursor == node degree
__device__ int g_cntB[N_EDGES];            // cursor == edge degree
__device__ __align__(16) int g_padN[N_NODES * PAD];   // node -> edge ids
__device__ __align__(16) int g_padE[N_EDGES * PAD];   // edge -> node ids

// ---------------------------------------------------------------------------
__global__ void zero_cnt_kernel() {
    int i = blockIdx.x * blockDim.x + threadIdx.x;
    if (i < N_NODES) g_cntN[i] = 0;
    if (i < N_EDGES) g_cntB[i] = 0;
}

// ---------------------------------------------------------------------------
// Merged bucketed fill: 4 entries per thread (int4 index loads) => 8
// independent atomic->store chains per thread for latency hiding.
// ---------------------------------------------------------------------------
__global__ void fill_kernel(const int* __restrict__ hei) {
    int t = blockIdx.x * blockDim.x + threadIdx.x;
    int i = 4 * t;
    if (i >= NNZV) return;
    int4 nd = *reinterpret_cast<const int4*>(hei + i);
    int4 ed = *reinterpret_cast<const int4*>(hei + NNZV + i);

    int pE0 = atomicAdd(&g_cntB[ed.x], 1);
    int pE1 = atomicAdd(&g_cntB[ed.y], 1);
    int pE2 = atomicAdd(&g_cntB[ed.z], 1);
    int pE3 = atomicAdd(&g_cntB[ed.w], 1);
    int pN0 = atomicAdd(&g_cntN[nd.x], 1);
    int pN1 = atomicAdd(&g_cntN[nd.y], 1);
    int pN2 = atomicAdd(&g_cntN[nd.z], 1);
    int pN3 = atomicAdd(&g_cntN[nd.w], 1);

    if (pE0 < PAD) g_padE[ed.x * PAD + pE0] = nd.x;
    if (pE1 < PAD) g_padE[ed.y * PAD + pE1] = nd.y;
    if (pE2 < PAD) g_padE[ed.z * PAD + pE2] = nd.z;
    if (pE3 < PAD) g_padE[ed.w * PAD + pE3] = nd.w;
    if (pN0 < PAD) g_padN[nd.x * PAD + pN0] = ed.x;
    if (pN1 < PAD) g_padN[nd.y * PAD + pN1] = ed.y;
    if (pN2 < PAD) g_padN[nd.z * PAD + pN2] = ed.z;
    if (pN3 < PAD) g_padN[nd.w * PAD + pN3] = ed.w;
}

// ---------------------------------------------------------------------------
// Tiled SGEMM: h[N,128] = x[N,128] @ W[128,128], fp16 output.
// ---------------------------------------------------------------------------
#define BM 128
#define BN 128
#define BK 32
__global__ __launch_bounds__(256) void sgemm_kernel(const float* __restrict__ x,
                                                    const float* __restrict__ w) {
    __shared__ float xs[BK][BM + 4];
    __shared__ float ws[BK][BN + 4];

    const int tid = threadIdx.x;
    const int tx = tid & 15;
    const int ty = tid >> 4;
    const int row0 = blockIdx.x * BM;

    float acc[8][8];
    #pragma unroll
    for (int i = 0; i < 8; i++)
        #pragma unroll
        for (int j = 0; j < 8; j++) acc[i][j] = 0.f;

    for (int k0 = 0; k0 < D_IN; k0 += BK) {
        #pragma unroll
        for (int r = 0; r < 4; r++) {
            int q = tid + 256 * r;
            int rr = q >> 3;
            int cc = (q & 7) * 4;
            int grow = row0 + rr;
            float4 xv = make_float4(0.f, 0.f, 0.f, 0.f);
            if (grow < N_NODES)
                xv = *reinterpret_cast<const float4*>(x + (size_t)grow * D_IN + k0 + cc);
            xs[cc + 0][rr] = xv.x;
            xs[cc + 1][rr] = xv.y;
            xs[cc + 2][rr] = xv.z;
            xs[cc + 3][rr] = xv.w;
        }
        #pragma unroll
        for (int r = 0; r < 4; r++) {
            int q = tid + 256 * r;
            int rr = q >> 5;
            int cc = (q & 31) * 4;
            float4 wv = *reinterpret_cast<const float4*>(w + (size_t)(k0 + rr) * D_OUT + cc);
            *reinterpret_cast<float4*>(&ws[rr][cc]) = wv;
        }
        __syncthreads();

        #pragma unroll
        for (int k = 0; k < BK; k++) {
            float a[8], b[8];
            *reinterpret_cast<float4*>(a)     = *reinterpret_cast<const float4*>(&xs[k][8 * ty]);
            *reinterpret_cast<float4*>(a + 4) = *reinterpret_cast<const float4*>(&xs[k][8 * ty + 4]);
            *reinterpret_cast<float4*>(b)     = *reinterpret_cast<const float4*>(&ws[k][8 * tx]);
            *reinterpret_cast<float4*>(b + 4) = *reinterpret_cast<const float4*>(&ws[k][8 * tx + 4]);
            #pragma unroll
            for (int i = 0; i < 8; i++)
                #pragma unroll
                for (int j = 0; j < 8; j++) acc[i][j] += a[i] * b[j];
        }
        __syncthreads();
    }

    #pragma unroll
    for (int i = 0; i < 8; i++) {
        int grow = row0 + 8 * ty + i;
        if (grow < N_NODES) {
            __half2 hp[4];
            hp[0] = __float22half2_rn(make_float2(acc[i][0], acc[i][1]));
            hp[1] = __float22half2_rn(make_float2(acc[i][2], acc[i][3]));
            hp[2] = __float22half2_rn(make_float2(acc[i][4], acc[i][5]));
            hp[3] = __float22half2_rn(make_float2(acc[i][6], acc[i][7]));
            *reinterpret_cast<uint4*>(&g_hh2[(size_t)grow * 64 + 4 * tx]) =
                *reinterpret_cast<uint4*>(hp);
        }
    }
}

// ---------------------------------------------------------------------------
// Gather-accumulate core: 16-lane group, uint4 gathers, fp16 chunk
// accumulation (<=8 neighbors per chunk) flushed into fp32.
// ---------------------------------------------------------------------------
__device__ __forceinline__ void gather_sum(
    const uint4* __restrict__ feat4, const int* __restrict__ adj,
    int base, int deg, int sub,
    float2& f0, float2& f1, float2& f2, float2& f3)
{
    const __half2 hz = __float2half2_rn(0.f);
    for (int j0 = 0; j0 < deg; j0 += 16) {
        int idx = (j0 + sub < deg) ? __ldg(&adj[base + j0 + sub]) : 0;
        int m = min(16, deg - j0);
        // chunk A: neighbors [0, min(m,8))
        {
            __half2 h0 = hz, h1 = hz, h2 = hz, h3 = hz;
            int m1 = min(m, 8);
            #pragma unroll 4
            for (int j = 0; j < m1; j++) {
                int r = __shfl_sync(0xffffffffu, idx, j, 16);
                uint4 raw = feat4[r * 16 + sub];
                h0 = __hadd2(h0, *reinterpret_cast<__half2*>(&raw.x));
                h1 = __hadd2(h1, *reinterpret_cast<__half2*>(&raw.y));
                h2 = __hadd2(h2, *reinterpret_cast<__half2*>(&raw.z));
                h3 = __hadd2(h3, *reinterpret_cast<__half2*>(&raw.w));
            }
            float2 t;
            t = __half22float2(h0); f0.x += t.x; f0.y += t.y;
            t = __half22float2(h1); f1.x += t.x; f1.y += t.y;
            t = __half22float2(h2); f2.x += t.x; f2.y += t.y;
            t = __half22float2(h3); f3.x += t.x; f3.y += t.y;
        }
        // chunk B: neighbors [8, m)
        if (m > 8) {
            __half2 h0 = hz, h1 = hz, h2 = hz, h3 = hz;
            #pragma unroll 4
            for (int j = 8; j < m; j++) {
                int r = __shfl_sync(0xffffffffu, idx, j, 16);
                uint4 raw = feat4[r * 16 + sub];
                h0 = __hadd2(h0, *reinterpret_cast<__half2*>(&raw.x));
                h1 = __hadd2(h1, *reinterpret_cast<__half2*>(&raw.y));
                h2 = __hadd2(h2, *reinterpret_cast<__half2*>(&raw.z));
                h3 = __hadd2(h3, *reinterpret_cast<__half2*>(&raw.w));
            }
            float2 t;
            t = __half22float2(h0); f0.x += t.x; f0.y += t.y;
            t = __half22float2(h1); f1.x += t.x; f1.y += t.y;
            t = __half22float2(h2); f2.x += t.x; f2.y += t.y;
            t = __half22float2(h3); f3.x += t.x; f3.y += t.y;
        }
    }
}

// ---------------------------------------------------------------------------
// Pass 1: 16-lane group per hyperedge (2/warp).
// e_feat[e] = (1/B_e) * sum_{i in e} h[i], fp16 out.
// ---------------------------------------------------------------------------
__global__ __launch_bounds__(256) void pass1_kernel() {
    const int lane = threadIdx.x & 31;
    const int sub  = lane & 15;
    const int grp  = lane >> 4;
    const int warp = (blockIdx.x * blockDim.x + threadIdx.x) >> 5;
    const int e = warp * 2 + grp;
    if (e >= N_EDGES) return;

    int deg = min(g_cntB[e], PAD);
    float2 f0 = {0.f, 0.f}, f1 = {0.f, 0.f}, f2 = {0.f, 0.f}, f3 = {0.f, 0.f};
    gather_sum(reinterpret_cast<const uint4*>(g_hh2), g_padE, e * PAD, deg, sub,
               f0, f1, f2, f3);

    float binv = (deg > 0) ? 1.0f / (float)deg : 0.f;
    __half2 hp[4];
    hp[0] = __float22half2_rn(make_float2(f0.x * binv, f0.y * binv));
    hp[1] = __float22half2_rn(make_float2(f1.x * binv, f1.y * binv));
    hp[2] = __float22half2_rn(make_float2(f2.x * binv, f2.y * binv));
    hp[3] = __float22half2_rn(make_float2(f3.x * binv, f3.y * binv));
    reinterpret_cast<uint4*>(g_efh2)[e * 16 + sub] = *reinterpret_cast<uint4*>(hp);
}

// ---------------------------------------------------------------------------
// Pass 2: 16-lane group per node (2/warp).
// out[i] = (1/D_i) * sum_{e ni i} e_feat[e] + bias, fp32 out.
// ---------------------------------------------------------------------------
__global__ __launch_bounds__(256) void pass2_kernel(float4* __restrict__ out4,
                                                    const float4* __restrict__ bias4) {
    const int lane = threadIdx.x & 31;
    const int sub  = lane & 15;
    const int grp  = lane >> 4;
    const int warp = (blockIdx.x * blockDim.x + threadIdx.x) >> 5;
    const int nd = warp * 2 + grp;
    if (nd >= N_NODES) return;

    int deg = min(g_cntN[nd], PAD);
    float2 f0 = {0.f, 0.f}, f1 = {0.f, 0.f}, f2 = {0.f, 0.f}, f3 = {0.f, 0.f};
    gather_sum(reinterpret_cast<const uint4*>(g_efh2), g_padN, nd * PAD, deg, sub,
               f0, f1, f2, f3);

    float dinv = (deg > 0) ? 1.0f / (float)deg : 0.f;
    float4 b0 = bias4[sub * 2];
    float4 b1 = bias4[sub * 2 + 1];
    out4[(size_t)nd * 32 + sub * 2] =
        make_float4(f0.x * dinv + b0.x, f0.y * dinv + b0.y,
                    f1.x * dinv + b0.z, f1.y * dinv + b0.w);
    out4[(size_t)nd * 32 + sub * 2 + 1] =
        make_float4(f2.x * dinv + b1.x, f2.y * dinv + b1.y,
                    f3.x * dinv + b1.z, f3.y * dinv + b1.w);
}

// ---------------------------------------------------------------------------
// Streams/events (created once, outside capture, on first eager call).
// ---------------------------------------------------------------------------
static cudaStream_t g_side = nullptr;
static cudaEvent_t  g_evFork = nullptr, g_evGemm = nullptr;

extern "C" void kernel_launch(void* const* d_in, const int* in_sizes, int n_in,
                              void* d_out, int out_size) {
    const float* x    = (const float*)d_in[0];
    const float* w    = (const float*)d_in[1];
    const float* bias = (const float*)d_in[2];
    const int*   hei  = (const int*)d_in[3];
    float* out = (float*)d_out;

    (void)in_sizes; (void)n_in; (void)out_size;

    if (g_side == nullptr) {
        cudaStreamCreateWithFlags(&g_side, cudaStreamNonBlocking);
        cudaEventCreateWithFlags(&g_evFork, cudaEventDisableTiming);
        cudaEventCreateWithFlags(&g_evGemm, cudaEventDisableTiming);
    }

    // Fork side stream: SGEMM co-runs with zero + fill.
    cudaEventRecord(g_evFork, 0);
    cudaStreamWaitEvent(g_side, g_evFork, 0);
    sgemm_kernel<<<(N_NODES + BM - 1) / BM, 256, 0, g_side>>>(x, w);
    cudaEventRecord(g_evGemm, g_side);

    // Main stream: merged CSR build, then passes.
    zero_cnt_kernel<<<(N_NODES + 255) / 256, 256>>>();
    fill_kernel<<<(NNZV / 4 + 255) / 256, 256>>>(hei);
    cudaStreamWaitEvent(0, g_evGemm, 0);         // pass1 needs h + padE
    pass1_kernel<<<(N_EDGES + 15) / 16, 256>>>();
    pass2_kernel<<<(N_NODES + 15) / 16, 256>>>(
        reinterpret_cast<float4*>(out),
        reinterpret_cast<const float4*>(bias));
}

// round 10
// speedup vs baseline: 1.3406x; 1.3406x over previous
#include <cuda_runtime.h>
#include <cuda_fp16.h>
#include <mma.h>

using namespace nvcuda;

#define N_NODES 100000
#define N_EDGES 100000
#define NNZV    1600000
#define D_IN    128
#define D_OUT   128
#define PAD     64        // slots per row; Poisson(16) => P(deg>64) ~ 1e-20/bucket

#define GEMM_SMEM (2 * 128 * 136 * 2)   // A + B halves = 69632 B (reused as float C)

// ---- scratch (device globals; allocation is forbidden) ----
__device__ __align__(16) __half2 g_hh2[N_NODES * 64];   // x @ W, fp16   (25.6 MB)
__device__ __align__(16) __half2 g_efh2[N_EDGES * 64];  // e_feat, fp16  (25.6 MB)
__device__ int g_cntN[N_NODES];            // cursor == node degree
__device__ int g_cntB[N_EDGES];            // cursor == edge degree
__device__ __align__(16) int g_padN[N_NODES * PAD];   // node -> edge ids
__device__ __align__(16) int g_padE[N_EDGES * PAD];   // edge -> node ids

// ---------------------------------------------------------------------------
__global__ void zero_cnt_kernel() {
    int i = blockIdx.x * blockDim.x + threadIdx.x;
    if (i < N_NODES) g_cntN[i] = 0;
    if (i < N_EDGES) g_cntB[i] = 0;
}

// ---------------------------------------------------------------------------
// Merged bucketed fill (R8 version — best measured): 2 entries/thread.
// ---------------------------------------------------------------------------
__global__ void fill_kernel(const int* __restrict__ hei) {
    int t = blockIdx.x * blockDim.x + threadIdx.x;
    int i = 2 * t;
    if (i >= NNZV) return;
    int2 nd = *reinterpret_cast<const int2*>(hei + i);
    int2 ed = *reinterpret_cast<const int2*>(hei + NNZV + i);
    int pE0 = atomicAdd(&g_cntB[ed.x], 1);
    if (pE0 < PAD) g_padE[ed.x * PAD + pE0] = nd.x;
    int pN0 = atomicAdd(&g_cntN[nd.x], 1);
    if (pN0 < PAD) g_padN[nd.x * PAD + pN0] = ed.x;
    int pE1 = atomicAdd(&g_cntB[ed.y], 1);
    if (pE1 < PAD) g_padE[ed.y * PAD + pE1] = nd.y;
    int pN1 = atomicAdd(&g_cntN[nd.y], 1);
    if (pN1 < PAD) g_padN[nd.y * PAD + pN1] = ed.y;
}

// ---------------------------------------------------------------------------
// Tensor-core GEMM: h[N,128] = fp16(x) @ fp16(W), fp32 accumulate, fp16 out.
// One block = 128 rows. A/B tiles in smem (fp16, ld=136), C staged through the
// same smem (float, ld=136) for the fp16 conversion.
// ---------------------------------------------------------------------------
__global__ __launch_bounds__(256) void gemm_wmma_kernel(const float* __restrict__ x,
                                                        const float* __restrict__ w) {
    extern __shared__ char smem[];
    half* As = reinterpret_cast<half*>(smem);            // [128][136]
    half* Bs = As + 128 * 136;                           // [128][136]
    float* Cs = reinterpret_cast<float*>(smem);          // [128][136] (reuse)

    const int tid  = threadIdx.x;
    const int wid  = tid >> 5;
    const int row0 = blockIdx.x * 128;

    // Load + convert x tile and W into smem fp16.
    #pragma unroll
    for (int it = 0; it < 16; it++) {
        int q  = tid + 256 * it;       // 0..4095
        int r  = q >> 5;               // row 0..127
        int c4 = q & 31;               // float4 column
        float4 v = make_float4(0.f, 0.f, 0.f, 0.f);
        if (row0 + r < N_NODES)
            v = *reinterpret_cast<const float4*>(x + (size_t)(row0 + r) * D_IN + c4 * 4);
        __half2 p0 = __floats2half2_rn(v.x, v.y);
        __half2 p1 = __floats2half2_rn(v.z, v.w);
        uint2 pk = make_uint2(*reinterpret_cast<unsigned*>(&p0),
                              *reinterpret_cast<unsigned*>(&p1));
        *reinterpret_cast<uint2*>(&As[r * 136 + c4 * 4]) = pk;

        float4 wv = *reinterpret_cast<const float4*>(w + (size_t)r * D_OUT + c4 * 4);
        __half2 q0 = __floats2half2_rn(wv.x, wv.y);
        __half2 q1 = __floats2half2_rn(wv.z, wv.w);
        uint2 wk = make_uint2(*reinterpret_cast<unsigned*>(&q0),
                              *reinterpret_cast<unsigned*>(&q1));
        *reinterpret_cast<uint2*>(&Bs[r * 136 + c4 * 4]) = wk;
    }
    __syncthreads();

    // Each warp owns a 16-row band x all 8 column tiles.
    wmma::fragment<wmma::accumulator, 16, 16, 16, float> acc[8];
    #pragma unroll
    for (int n = 0; n < 8; n++) wmma::fill_fragment(acc[n], 0.f);

    #pragma unroll
    for (int k = 0; k < 8; k++) {
        wmma::fragment<wmma::matrix_a, 16, 16, 16, half, wmma::row_major> a;
        wmma::load_matrix_sync(a, As + (wid * 16) * 136 + k * 16, 136);
        #pragma unroll
        for (int n = 0; n < 8; n++) {
            wmma::fragment<wmma::matrix_b, 16, 16, 16, half, wmma::row_major> b;
            wmma::load_matrix_sync(b, Bs + (k * 16) * 136 + n * 16, 136);
            wmma::mma_sync(acc[n], a, b, acc[n]);
        }
    }
    __syncthreads();    // all reads of As/Bs done before reuse as Cs

    #pragma unroll
    for (int n = 0; n < 8; n++)
        wmma::store_matrix_sync(Cs + (wid * 16) * 136 + n * 16, acc[n], 136,
                                wmma::mem_row_major);
    __syncthreads();

    // Convert C to fp16 global.
    #pragma unroll
    for (int it = 0; it < 16; it++) {
        int q  = tid + 256 * it;
        int r  = q >> 5;
        int c4 = q & 31;
        if (row0 + r < N_NODES) {
            float4 v = *reinterpret_cast<const float4*>(&Cs[r * 136 + c4 * 4]);
            __half2 p0 = __floats2half2_rn(v.x, v.y);
            __half2 p1 = __floats2half2_rn(v.z, v.w);
            uint2 pk = make_uint2(*reinterpret_cast<unsigned*>(&p0),
                                  *reinterpret_cast<unsigned*>(&p1));
            *reinterpret_cast<uint2*>(&g_hh2[(size_t)(row0 + r) * 64 + c4 * 2]) = pk;
        }
    }
}

// ---------------------------------------------------------------------------
// Pass 1 (R7 version): 16-lane group per hyperedge, uint4 gathers, fp32 acc.
// ---------------------------------------------------------------------------
__global__ __launch_bounds__(256) void pass1_kernel() {
    const int lane = threadIdx.x & 31;
    const int sub  = lane & 15;
    const int grp  = lane >> 4;
    const int warp = (blockIdx.x * blockDim.x + threadIdx.x) >> 5;
    const int e = warp * 2 + grp;
    if (e >= N_EDGES) return;

    int deg = min(g_cntB[e], PAD);
    int base = e * PAD;
    const uint4* __restrict__ h4 = reinterpret_cast<const uint4*>(g_hh2);

    float acc[8];
    #pragma unroll
    for (int c = 0; c < 8; c++) acc[c] = 0.f;

    for (int j0 = 0; j0 < deg; j0 += 16) {
        int idx = (j0 + sub < deg) ? __ldg(&g_padE[base + j0 + sub]) : 0;
        int m = min(16, deg - j0);
        #pragma unroll 4
        for (int j = 0; j < m; j++) {
            int node = __shfl_sync(0xffffffffu, idx, j, 16);
            uint4 raw = h4[node * 16 + sub];
            float2 f0 = __half22float2(*reinterpret_cast<__half2*>(&raw.x));
            float2 f1 = __half22float2(*reinterpret_cast<__half2*>(&raw.y));
            float2 f2 = __half22float2(*reinterpret_cast<__half2*>(&raw.z));
            float2 f3 = __half22float2(*reinterpret_cast<__half2*>(&raw.w));
            acc[0] += f0.x; acc[1] += f0.y;
            acc[2] += f1.x; acc[3] += f1.y;
            acc[4] += f2.x; acc[5] += f2.y;
            acc[6] += f3.x; acc[7] += f3.y;
        }
    }
    float binv = (deg > 0) ? 1.0f / (float)deg : 0.f;
    __half2 hp[4];
    hp[0] = __float22half2_rn(make_float2(acc[0] * binv, acc[1] * binv));
    hp[1] = __float22half2_rn(make_float2(acc[2] * binv, acc[3] * binv));
    hp[2] = __float22half2_rn(make_float2(acc[4] * binv, acc[5] * binv));
    hp[3] = __float22half2_rn(make_float2(acc[6] * binv, acc[7] * binv));
    reinterpret_cast<uint4*>(g_efh2)[e * 16 + sub] = *reinterpret_cast<uint4*>(hp);
}

// ---------------------------------------------------------------------------
// Pass 2 (R7 version): 16-lane group per node, fp32 out + bias.
// ---------------------------------------------------------------------------
__global__ __launch_bounds__(256) void pass2_kernel(float4* __restrict__ out4,
                                                    const float4* __restrict__ bias4) {
    const int lane = threadIdx.x & 31;
    const int sub  = lane & 15;
    const int grp  = lane >> 4;
    const int warp = (blockIdx.x * blockDim.x + threadIdx.x) >> 5;
    const int nd = warp * 2 + grp;
    if (nd >= N_NODES) return;

    int deg = min(g_cntN[nd], PAD);
    int base = nd * PAD;
    const uint4* __restrict__ ef4 = reinterpret_cast<const uint4*>(g_efh2);

    float acc[8];
    #pragma unroll
    for (int c = 0; c < 8; c++) acc[c] = 0.f;

    for (int j0 = 0; j0 < deg; j0 += 16) {
        int idx = (j0 + sub < deg) ? __ldg(&g_padN[base + j0 + sub]) : 0;
        int m = min(16, deg - j0);
        #pragma unroll 4
        for (int j = 0; j < m; j++) {
            int e = __shfl_sync(0xffffffffu, idx, j, 16);
            uint4 raw = ef4[e * 16 + sub];
            float2 f0 = __half22float2(*reinterpret_cast<__half2*>(&raw.x));
            float2 f1 = __half22float2(*reinterpret_cast<__half2*>(&raw.y));
            float2 f2 = __half22float2(*reinterpret_cast<__half2*>(&raw.z));
            float2 f3 = __half22float2(*reinterpret_cast<__half2*>(&raw.w));
            acc[0] += f0.x; acc[1] += f0.y;
            acc[2] += f1.x; acc[3] += f1.y;
            acc[4] += f2.x; acc[5] += f2.y;
            acc[6] += f3.x; acc[7] += f3.y;
        }
    }
    float dinv = (deg > 0) ? 1.0f / (float)deg : 0.f;
    float4 b0 = bias4[sub * 2];
    float4 b1 = bias4[sub * 2 + 1];
    out4[(size_t)nd * 32 + sub * 2] =
        make_float4(acc[0] * dinv + b0.x, acc[1] * dinv + b0.y,
                    acc[2] * dinv + b0.z, acc[3] * dinv + b0.w);
    out4[(size_t)nd * 32 + sub * 2 + 1] =
        make_float4(acc[4] * dinv + b1.x, acc[5] * dinv + b1.y,
                    acc[6] * dinv + b1.z, acc[7] * dinv + b1.w);
}

// ---------------------------------------------------------------------------
// Streams/events + one-time attribute setup (outside capture, first eager call).
// ---------------------------------------------------------------------------
static cudaStream_t g_side = nullptr;
static cudaEvent_t  g_evFork = nullptr, g_evGemm = nullptr;

extern "C" void kernel_launch(void* const* d_in, const int* in_sizes, int n_in,
                              void* d_out, int out_size) {
    const float* x    = (const float*)d_in[0];
    const float* w    = (const float*)d_in[1];
    const float* bias = (const float*)d_in[2];
    const int*   hei  = (const int*)d_in[3];
    float* out = (float*)d_out;

    (void)in_sizes; (void)n_in; (void)out_size;

    if (g_side == nullptr) {
        cudaStreamCreateWithFlags(&g_side, cudaStreamNonBlocking);
        cudaEventCreateWithFlags(&g_evFork, cudaEventDisableTiming);
        cudaEventCreateWithFlags(&g_evGemm, cudaEventDisableTiming);
        cudaFuncSetAttribute(gemm_wmma_kernel,
                             cudaFuncAttributeMaxDynamicSharedMemorySize, GEMM_SMEM);
    }

    // Fork side stream: tensor-core GEMM co-runs with zero + fill.
    cudaEventRecord(g_evFork, 0);
    cudaStreamWaitEvent(g_side, g_evFork, 0);
    gemm_wmma_kernel<<<(N_NODES + 127) / 128, 256, GEMM_SMEM, g_side>>>(x, w);
    cudaEventRecord(g_evGemm, g_side);

    // Main stream: merged CSR build, then passes.
    zero_cnt_kernel<<<(N_NODES + 255) / 256, 256>>>();
    fill_kernel<<<(NNZV / 2 + 255) / 256, 256>>>(hei);
    cudaStreamWaitEvent(0, g_evGemm, 0);         // pass1 needs h + padE
    pass1_kernel<<<(N_EDGES + 15) / 16, 256>>>();
    pass2_kernel<<<(N_NODES + 15) / 16, 256>>>(
        reinterpret_cast<float4*>(out),
        reinterpret_cast<const float4*>(bias));
}